// round 11
// baseline (speedup 1.0000x reference)
#include <cuda_runtime.h>
#include <cuda_fp16.h>

#define NV 100000
#define NE 1600000
#define VERT_BLOCKS ((NV + 127) / 128)

// Packed per-vertex projection record: one 32B L2 sector per gather.
//   w.x = P0 (fp32), w.y = h2(P1,P2), w.z = h2(P3,P4), w.w = h2(P5,P6), w4 = h2(P7,P8)
struct __align__(32) PRec16 {
    uint4 w;
    unsigned int w4;
    unsigned int pad[3];
};

__device__ PRec16 g_P16[NV];
__device__ float4 g_self[NV]; // (selfMag, selfT1, selfT2, -)
__device__ float4 g_acc[NV];  // (sum_m0, sum_mv1, sum_mv2, deg)

__device__ __forceinline__ void l2_prefetch(const char* p) {
    asm volatile("prefetch.global.L2 [%0];" :: "l"(p));
}
__device__ __forceinline__ unsigned int pack2(float a, float b) {
    __half2 h = __floats2half2_rn(a, b);
    return *(unsigned int*)&h;
}

// ---------------------------------------------------------------------------
// Kernel 0: fire-and-forget L2 warm of the edge streams (25.6MB = 200k lines)
// + zero the accumulators (moved out of precompute). Fills complete in the
// background while precompute (DRAM ~21% busy) runs.
// ---------------------------------------------------------------------------
__global__ void __launch_bounds__(256)
prefetch_kernel(const char* __restrict__ edge_index,
                const char* __restrict__ angles,
                const char* __restrict__ transporters) {
    unsigned int gtid = blockIdx.x * 256 + threadIdx.x;
    if (gtid < 100000) {
        l2_prefetch(edge_index + (size_t)gtid * 128);
        g_acc[gtid] = make_float4(0.f, 0.f, 0.f, 0.f);
    } else if (gtid < 150000) {
        l2_prefetch(angles + (size_t)(gtid - 100000) * 128);
    } else if (gtid < 200000) {
        l2_prefetch(transporters + (size_t)(gtid - 150000) * 128);
    }
}

// ---------------------------------------------------------------------------
// Kernel 1 (R4-proven, no prefetch): per-vertex projections via smem staging.
// ---------------------------------------------------------------------------
__global__ void __launch_bounds__(128)
precompute_kernel(const float* __restrict__ x,
                  const float* __restrict__ w_self0,
                  const float* __restrict__ w_n00,
                  const float* __restrict__ w_n10,
                  const float* __restrict__ w_self11,
                  const float* __restrict__ w_n01,
                  const float* __restrict__ w_n11) {
    __shared__ float sx[128 * 49];

    int base = blockIdx.x * 128;
    int nV = NV - base; if (nV > 128) nV = 128;

    const float4* xv4 = (const float4*)(x + (size_t)base * 48);
    int nf4 = nV * 12;
    for (int j = threadIdx.x; j < nf4; j += 128) {
        float4 val = xv4[j];
        int row = j / 12;
        int col = (j % 12) * 4;
        float* d = &sx[row * 49 + col];
        d[0] = val.x; d[1] = val.y; d[2] = val.z; d[3] = val.w;
    }
    __syncthreads();

    int v = base + threadIdx.x;
    if (v >= NV) return;
    const float* xv = &sx[threadIdx.x * 49];

    float P0 = 0.f, P3 = 0.f, P4 = 0.f, P9 = 0.f;
#pragma unroll
    for (int i = 0; i < 16; i++) {
        float xi = xv[i];
        P0 = fmaf(xi, __ldg(&w_n00[i]), P0);
        P3 = fmaf(xi, __ldg(&w_n01[2 * i + 0]), P3);
        P4 = fmaf(xi, __ldg(&w_n01[2 * i + 1]), P4);
        P9 = fmaf(xi, __ldg(&w_self0[i]), P9);
    }

    float a0 = 0.f, b0 = 0.f, a1 = 0.f, b1 = 0.f;
    float ap = 0.f, bp = 0.f, aq = 0.f, bq = 0.f;
    float ar = 0.f, br = 0.f, as_ = 0.f, bs = 0.f;
    float t1s = 0.f, t2s = 0.f;
#pragma unroll
    for (int c = 0; c < 16; c++) {
        float a = xv[16 + 2 * c + 0];
        float b = xv[16 + 2 * c + 1];
        float w0 = __ldg(&w_n10[2 * c + 0]);
        float w1 = __ldg(&w_n10[2 * c + 1]);
        a0 = fmaf(a, w0, a0); b0 = fmaf(b, w0, b0);
        a1 = fmaf(a, w1, a1); b1 = fmaf(b, w1, b1);
        float p = __ldg(&w_n11[4 * c + 0]);
        float q = __ldg(&w_n11[4 * c + 1]);
        float r = __ldg(&w_n11[4 * c + 2]);
        float s = __ldg(&w_n11[4 * c + 3]);
        ap = fmaf(a, p, ap); bp = fmaf(b, p, bp);
        aq = fmaf(a, q, aq); bq = fmaf(b, q, bq);
        ar = fmaf(a, r, ar); br = fmaf(b, r, br);
        as_ = fmaf(a, s, as_); bs = fmaf(b, s, bs);
        float sa = __ldg(&w_self11[2 * c + 0]);
        float sb = __ldg(&w_self11[2 * c + 1]);
        t1s = fmaf(a, sa, t1s); t1s = fmaf(-b, sb, t1s);
        t2s = fmaf(b, sa, t2s); t2s = fmaf(a, sb, t2s);
    }

    PRec16 rec;
    rec.w = make_uint4(__float_as_uint(P0),
                       pack2(a0 + b1, b0 - a1),     // (P1, P2)
                       pack2(P3, P4),               // (P3, P4)
                       pack2(ap - bq, bp + aq));    // (P5, P6)
    rec.w4 = pack2(ar + bs, br - as_);              // (P7, P8)
    rec.pad[0] = rec.pad[1] = rec.pad[2] = 0u;
    g_P16[v] = rec;
    g_self[v] = make_float4(P9, t1s, t2s, 0.f);
}

// ---------------------------------------------------------------------------
// Kernel 2: 4 edges per thread; single-sector fp16 gather; one v4 RED/edge.
// ---------------------------------------------------------------------------
__device__ __forceinline__ void edge_msg(int src, float t, float g,
                                         float& m0, float& mv1, float& mv2) {
    float st, ct, sg, cg;
    __sincosf(t, &st, &ct);
    __sincosf(g, &sg, &cg);
    float cdt = fmaf(ct, cg, st * sg);     // cos(t-g)
    float sdt = fmaf(st, cg, -ct * sg);    // sin(t-g)
    float c2 = fmaf(ct, cdt, -st * sdt);   // cos(2t-g)
    float s2 = fmaf(st, cdt, ct * sdt);    // sin(2t-g)

    const PRec16& pr = g_P16[src];
    uint4 w = pr.w;
    unsigned int w4 = pr.w4;
    float  p0  = __uint_as_float(w.x);
    float2 p12 = __half22float2(*(const __half2*)&w.y);
    float2 p34 = __half22float2(*(const __half2*)&w.z);
    float2 p56 = __half22float2(*(const __half2*)&w.w);
    float2 p78 = __half22float2(*(const __half2*)&w4);

    m0  = p0 + fmaf(p12.x, cdt, p12.y * sdt);
    mv1 = fmaf(p34.x, ct, -p34.y * st) + fmaf(p56.x, cg, -p56.y * sg)
        + fmaf(p78.x, c2, p78.y * s2);
    mv2 = fmaf(p34.x, st, p34.y * ct) + fmaf(p56.x, sg, p56.y * cg)
        + fmaf(-p78.y, c2, p78.x * s2);
}

__global__ void __launch_bounds__(256)
edge_kernel(const int* __restrict__ edge_index,
            const float* __restrict__ angles,
            const float* __restrict__ transporters) {
    int i = blockIdx.x * blockDim.x + threadIdx.x;   // quad index
    if (i >= NE / 4) return;

    int4   s4 = ((const int4*)edge_index)[i];
    int4   d4 = ((const int4*)(edge_index + NE))[i];
    float4 t4 = ((const float4*)angles)[i];
    float4 g4 = ((const float4*)transporters)[i];

    float m0, mv1, mv2;
#define DO_EDGE(SRC, DST, T, G)                                              \
    edge_msg(SRC, T, G, m0, mv1, mv2);                                       \
    asm volatile("red.relaxed.gpu.global.add.v4.f32 [%0], {%1, %2, %3, %4};" \
                 :: "l"(&g_acc[DST]), "f"(m0), "f"(mv1), "f"(mv2), "f"(1.0f) \
                 : "memory");

    DO_EDGE(s4.x, d4.x, t4.x, g4.x)
    DO_EDGE(s4.y, d4.y, t4.y, g4.y)
    DO_EDGE(s4.z, d4.z, t4.z, g4.z)
    DO_EDGE(s4.w, d4.w, t4.w, g4.w)
#undef DO_EDGE
}

// ---------------------------------------------------------------------------
// Kernel 3: one thread per OUTPUT ELEMENT (3*NV threads); coalesced streams.
// ---------------------------------------------------------------------------
__global__ void __launch_bounds__(256)
finalize_kernel(const float* __restrict__ e1,
                const float* __restrict__ e2,
                float* __restrict__ out) {
    int j = blockIdx.x * blockDim.x + threadIdx.x;
    if (j >= NV * 3) return;
    int v = j / 3;

    float4 acc = g_acc[v];
    float4 sf  = g_self[v];
    float inv = 1.0f / fmaxf(acc.w, 1.0f);

    float mag = fmaf(acc.x, inv, sf.x);
    float t1  = fmaf(acc.y, inv, sf.y);
    float t2  = fmaf(acc.z, inv, sf.z);
    float scale = 2.0f / (1.0f + __expf(-mag));

    out[j] = fmaf(t1, e1[j], t2 * e2[j]) * scale;
}

extern "C" void kernel_launch(void* const* d_in, const int* in_sizes, int n_in,
                              void* d_out, int out_size) {
    const float* x            = (const float*)d_in[0];
    const int*   edge_index   = (const int*)d_in[1];
    const float* angles       = (const float*)d_in[2];
    const float* transporters = (const float*)d_in[3];
    const float* e1           = (const float*)d_in[4];
    const float* e2           = (const float*)d_in[5];
    const float* w_self0      = (const float*)d_in[6];
    const float* w_n00        = (const float*)d_in[7];
    const float* w_n10        = (const float*)d_in[8];
    const float* w_self11     = (const float*)d_in[9];
    const float* w_n01        = (const float*)d_in[10];
    const float* w_n11        = (const float*)d_in[11];
    float*       out          = (float*)d_out;

    prefetch_kernel<<<(200000 + 255) / 256, 256>>>(
        (const char*)edge_index, (const char*)angles, (const char*)transporters);
    precompute_kernel<<<VERT_BLOCKS, 128>>>(x, w_self0, w_n00, w_n10,
                                            w_self11, w_n01, w_n11);
    edge_kernel<<<(NE / 4 + 255) / 256, 256>>>(edge_index, angles, transporters);
    finalize_kernel<<<(NV * 3 + 255) / 256, 256>>>(e1, e2, out);
}

// round 12
// speedup vs baseline: 1.0801x; 1.0801x over previous
#include <cuda_runtime.h>
#include <cuda_fp16.h>

#define NV 100000
#define NE 1600000
#define VERT_BLOCKS ((NV + 127) / 128)

// Packed per-vertex projection record: one 32B L2 sector per gather.
struct __align__(32) PRec16 {
    uint4 w;            // P0 fp32 | h2(P1,P2) | h2(P3,P4) | h2(P5,P6)
    unsigned int w4;    // h2(P7,P8)
    unsigned int pad[3];
};
// Combined accumulator + self record: one 32B line for finalize.
struct __align__(32) VRec {
    float4 acc;   // (sum_m0, sum_mv1, sum_mv2, deg) — RED target
    float4 self;  // (selfMag, selfT1, selfT2, -)
};

__device__ PRec16 g_P16[NV];
__device__ VRec   g_vs[NV];

__device__ __forceinline__ void l2_prefetch(const char* p) {
    asm volatile("prefetch.global.L2 [%0];" :: "l"(p));
}
__device__ __forceinline__ unsigned int pack2(float a, float b) {
    __half2 h = __floats2half2_rn(a, b);
    return *(unsigned int*)&h;
}

// Prefetch line map: 218750 lines total over 100k threads (~2.2 each).
//  [0,100000)        edge_index   (12.8MB)
//  [100000,150000)   angles       (6.4MB)
//  [150000,200000)   transporters (6.4MB)
//  [200000,209375)   e1           (1.2MB)
//  [209375,218750)   e2           (1.2MB)
__device__ __forceinline__ void prefetch_line(long long id,
                                              const char* ei, const char* an,
                                              const char* tr, const char* p1,
                                              const char* p2) {
    if (id < 100000)      l2_prefetch(ei + id * 128);
    else if (id < 150000) l2_prefetch(an + (id - 100000) * 128);
    else if (id < 200000) l2_prefetch(tr + (id - 150000) * 128);
    else if (id < 209375) l2_prefetch(p1 + (id - 200000) * 128);
    else if (id < 218750) l2_prefetch(p2 + (id - 209375) * 128);
}

// ---------------------------------------------------------------------------
// Kernel 1: per-vertex projections via smem staging. Prefetches are issued
// AFTER the staging sync (LSU queue empty) and overlap the FMA phase.
// ---------------------------------------------------------------------------
__global__ void __launch_bounds__(128)
precompute_kernel(const float* __restrict__ x,
                  const float* __restrict__ w_self0,
                  const float* __restrict__ w_n00,
                  const float* __restrict__ w_n10,
                  const float* __restrict__ w_self11,
                  const float* __restrict__ w_n01,
                  const float* __restrict__ w_n11,
                  const char* __restrict__ ei, const char* __restrict__ an,
                  const char* __restrict__ tr, const char* __restrict__ p1,
                  const char* __restrict__ p2) {
    __shared__ float sx[128 * 49];

    int base = blockIdx.x * 128;
    int nV = NV - base; if (nV > 128) nV = 128;

    const float4* xv4 = (const float4*)(x + (size_t)base * 48);
    int nf4 = nV * 12;
    for (int j = threadIdx.x; j < nf4; j += 128) {
        float4 val = xv4[j];
        int row = j / 12;
        int col = (j % 12) * 4;
        float* d = &sx[row * 49 + col];
        d[0] = val.x; d[1] = val.y; d[2] = val.z; d[3] = val.w;
    }
    __syncthreads();

    // Staging loads complete; fire L2 prefetches into an empty queue.
    {
        long long t = (long long)base + threadIdx.x;
        prefetch_line(t,           ei, an, tr, p1, p2);
        prefetch_line(t + 100000,  ei, an, tr, p1, p2);
        prefetch_line(t + 200000,  ei, an, tr, p1, p2);
    }

    int v = base + threadIdx.x;
    if (v >= NV) return;
    const float* xv = &sx[threadIdx.x * 49];

    float P0 = 0.f, P3 = 0.f, P4 = 0.f, P9 = 0.f;
#pragma unroll
    for (int i = 0; i < 16; i++) {
        float xi = xv[i];
        P0 = fmaf(xi, __ldg(&w_n00[i]), P0);
        P3 = fmaf(xi, __ldg(&w_n01[2 * i + 0]), P3);
        P4 = fmaf(xi, __ldg(&w_n01[2 * i + 1]), P4);
        P9 = fmaf(xi, __ldg(&w_self0[i]), P9);
    }

    float a0 = 0.f, b0 = 0.f, a1 = 0.f, b1 = 0.f;
    float ap = 0.f, bp = 0.f, aq = 0.f, bq = 0.f;
    float ar = 0.f, br = 0.f, as_ = 0.f, bs = 0.f;
    float t1s = 0.f, t2s = 0.f;
#pragma unroll
    for (int c = 0; c < 16; c++) {
        float a = xv[16 + 2 * c + 0];
        float b = xv[16 + 2 * c + 1];
        float w0 = __ldg(&w_n10[2 * c + 0]);
        float w1 = __ldg(&w_n10[2 * c + 1]);
        a0 = fmaf(a, w0, a0); b0 = fmaf(b, w0, b0);
        a1 = fmaf(a, w1, a1); b1 = fmaf(b, w1, b1);
        float p = __ldg(&w_n11[4 * c + 0]);
        float q = __ldg(&w_n11[4 * c + 1]);
        float r = __ldg(&w_n11[4 * c + 2]);
        float s = __ldg(&w_n11[4 * c + 3]);
        ap = fmaf(a, p, ap); bp = fmaf(b, p, bp);
        aq = fmaf(a, q, aq); bq = fmaf(b, q, bq);
        ar = fmaf(a, r, ar); br = fmaf(b, r, br);
        as_ = fmaf(a, s, as_); bs = fmaf(b, s, bs);
        float sa = __ldg(&w_self11[2 * c + 0]);
        float sb = __ldg(&w_self11[2 * c + 1]);
        t1s = fmaf(a, sa, t1s); t1s = fmaf(-b, sb, t1s);
        t2s = fmaf(b, sa, t2s); t2s = fmaf(a, sb, t2s);
    }

    PRec16 rec;
    rec.w = make_uint4(__float_as_uint(P0),
                       pack2(a0 + b1, b0 - a1),     // (P1, P2)
                       pack2(P3, P4),               // (P3, P4)
                       pack2(ap - bq, bp + aq));    // (P5, P6)
    rec.w4 = pack2(ar + bs, br - as_);              // (P7, P8)
    rec.pad[0] = rec.pad[1] = rec.pad[2] = 0u;
    g_P16[v] = rec;

    VRec vr;
    vr.acc  = make_float4(0.f, 0.f, 0.f, 0.f);
    vr.self = make_float4(P9, t1s, t2s, 0.f);
    g_vs[v] = vr;
}

// ---------------------------------------------------------------------------
// Kernel 2: 4 edges per thread; single-sector fp16 gather; one v4 RED/edge.
// ---------------------------------------------------------------------------
__device__ __forceinline__ void edge_msg(int src, float t, float g,
                                         float& m0, float& mv1, float& mv2) {
    float st, ct, sg, cg;
    __sincosf(t, &st, &ct);
    __sincosf(g, &sg, &cg);
    float cdt = fmaf(ct, cg, st * sg);     // cos(t-g)
    float sdt = fmaf(st, cg, -ct * sg);    // sin(t-g)
    float c2 = fmaf(ct, cdt, -st * sdt);   // cos(2t-g)
    float s2 = fmaf(st, cdt, ct * sdt);    // sin(2t-g)

    const PRec16& pr = g_P16[src];
    uint4 w = pr.w;
    unsigned int w4 = pr.w4;
    float  p0  = __uint_as_float(w.x);
    float2 p12 = __half22float2(*(const __half2*)&w.y);
    float2 p34 = __half22float2(*(const __half2*)&w.z);
    float2 p56 = __half22float2(*(const __half2*)&w.w);
    float2 p78 = __half22float2(*(const __half2*)&w4);

    m0  = p0 + fmaf(p12.x, cdt, p12.y * sdt);
    mv1 = fmaf(p34.x, ct, -p34.y * st) + fmaf(p56.x, cg, -p56.y * sg)
        + fmaf(p78.x, c2, p78.y * s2);
    mv2 = fmaf(p34.x, st, p34.y * ct) + fmaf(p56.x, sg, p56.y * cg)
        + fmaf(-p78.y, c2, p78.x * s2);
}

__global__ void __launch_bounds__(256)
edge_kernel(const int* __restrict__ edge_index,
            const float* __restrict__ angles,
            const float* __restrict__ transporters) {
    int i = blockIdx.x * blockDim.x + threadIdx.x;   // quad index
    if (i >= NE / 4) return;

    int4   s4 = ((const int4*)edge_index)[i];
    int4   d4 = ((const int4*)(edge_index + NE))[i];
    float4 t4 = ((const float4*)angles)[i];
    float4 g4 = ((const float4*)transporters)[i];

    float m0, mv1, mv2;
#define DO_EDGE(SRC, DST, T, G)                                              \
    edge_msg(SRC, T, G, m0, mv1, mv2);                                       \
    asm volatile("red.relaxed.gpu.global.add.v4.f32 [%0], {%1, %2, %3, %4};" \
                 :: "l"(&g_vs[DST].acc), "f"(m0), "f"(mv1), "f"(mv2),        \
                    "f"(1.0f) : "memory");

    DO_EDGE(s4.x, d4.x, t4.x, g4.x)
    DO_EDGE(s4.y, d4.y, t4.y, g4.y)
    DO_EDGE(s4.z, d4.z, t4.z, g4.z)
    DO_EDGE(s4.w, d4.w, t4.w, g4.w)
#undef DO_EDGE
}

// ---------------------------------------------------------------------------
// Kernel 3: one thread per OUTPUT ELEMENT; single 32B record per vertex.
// ---------------------------------------------------------------------------
__global__ void __launch_bounds__(256)
finalize_kernel(const float* __restrict__ e1,
                const float* __restrict__ e2,
                float* __restrict__ out) {
    int j = blockIdx.x * blockDim.x + threadIdx.x;
    if (j >= NV * 3) return;
    int v = j / 3;

    VRec vr = g_vs[v];
    float inv = 1.0f / fmaxf(vr.acc.w, 1.0f);

    float mag = fmaf(vr.acc.x, inv, vr.self.x);
    float t1  = fmaf(vr.acc.y, inv, vr.self.y);
    float t2  = fmaf(vr.acc.z, inv, vr.self.z);
    float scale = 2.0f / (1.0f + __expf(-mag));

    out[j] = fmaf(t1, e1[j], t2 * e2[j]) * scale;
}

extern "C" void kernel_launch(void* const* d_in, const int* in_sizes, int n_in,
                              void* d_out, int out_size) {
    const float* x            = (const float*)d_in[0];
    const int*   edge_index   = (const int*)d_in[1];
    const float* angles       = (const float*)d_in[2];
    const float* transporters = (const float*)d_in[3];
    const float* e1           = (const float*)d_in[4];
    const float* e2           = (const float*)d_in[5];
    const float* w_self0      = (const float*)d_in[6];
    const float* w_n00        = (const float*)d_in[7];
    const float* w_n10        = (const float*)d_in[8];
    const float* w_self11     = (const float*)d_in[9];
    const float* w_n01        = (const float*)d_in[10];
    const float* w_n11        = (const float*)d_in[11];
    float*       out          = (float*)d_out;

    precompute_kernel<<<VERT_BLOCKS, 128>>>(
        x, w_self0, w_n00, w_n10, w_self11, w_n01, w_n11,
        (const char*)edge_index, (const char*)angles, (const char*)transporters,
        (const char*)e1, (const char*)e2);
    edge_kernel<<<(NE / 4 + 255) / 256, 256>>>(edge_index, angles, transporters);
    finalize_kernel<<<(NV * 3 + 255) / 256, 256>>>(e1, e2, out);
}